// round 12
// baseline (speedup 1.0000x reference)
#include <cuda_runtime.h>

// ---------------------------------------------------------------------------
// Threshold_weights7: per-row top-2 margins over 8 predictors [N,128],
// softmax(margins/2) over 8 predictors, plus global max of predictors 0..6.
// Memory-bound: 512MB read. TWO rows per warp; ping-pong software pipeline at
// batch granularity (4 preds / 8 LDG.128 per batch) so 8 loads are in flight
// during EVERY compute phase. Persistent single-wave grid (148 SM x 3 blocks).
// ---------------------------------------------------------------------------

static constexpr int kC = 128;     // class dim
static constexpr int kGrid = 444;  // 148 SMs x 3 blocks/SM, single wave

__device__ unsigned g_max_key;  // zero-init at load; self-reset every call
__device__ unsigned g_ticket;

__device__ __forceinline__ unsigned f2key(float f) {
    unsigned u = __float_as_uint(f);
    return (u & 0x80000000u) ? ~u : (u | 0x80000000u);
}

// load 4 predictors' half-row (8 floats) for this lane: 8 x LDG.128
__device__ __forceinline__ void load_batch(float4* va, float4* vb,
                                           const float* const* pr, size_t base) {
#pragma unroll
    for (int p = 0; p < 4; p++) {
        va[p] = __ldcs(reinterpret_cast<const float4*>(pr[p] + base));
        vb[p] = __ldcs(reinterpret_cast<const float4*>(pr[p] + base + 4));
    }
}

// top-2 margin for one predictor (16-lane half-warp row)
__device__ __forceinline__ float margin16(float4 qa, float4 qb, int towner,
                                          int tq, int tsub, float& M1out) {
    float a1 = fmaxf(qa.x, qa.y), a2 = fminf(qa.x, qa.y);
    float b1 = fmaxf(qa.z, qa.w), b2 = fminf(qa.z, qa.w);
    float m1a = fmaxf(a1, b1);
    float m2a = fmaxf(fminf(a1, b1), fmaxf(a2, b2));
    float c1 = fmaxf(qb.x, qb.y), c2 = fminf(qb.x, qb.y);
    float d1 = fmaxf(qb.z, qb.w), d2 = fminf(qb.z, qb.w);
    float m1b = fmaxf(c1, d1);
    float m2b = fmaxf(fminf(c1, d1), fmaxf(c2, d2));
    float m1 = fmaxf(m1a, m1b);
    float m2 = fmaxf(fminf(m1a, m1b), fmaxf(m2a, m2b));

    float ta = (tsub == 0) ? qa.x : (tsub == 1) ? qa.y
             : (tsub == 2) ? qa.z : qa.w;
    float tb = (tsub == 0) ? qb.x : (tsub == 1) ? qb.y
             : (tsub == 2) ? qb.z : qb.w;
    float tl = tq ? tb : ta;
    float tv = __shfl_sync(0xffffffffu, tl, towner, 16);

#pragma unroll
    for (int off = 8; off; off >>= 1) {
        float o1 = __shfl_xor_sync(0xffffffffu, m1, off);
        float o2 = __shfl_xor_sync(0xffffffffu, m2, off);
        float n2 = fmaxf(fminf(m1, o1), fmaxf(m2, o2));
        m1 = fmaxf(m1, o1);
        m2 = n2;
    }
    M1out = m1;
    return (tv == m1) ? (m1 - m2) : 0.0f;  // exact-equality tie semantics
}

__global__ void __launch_bounds__(256, 3)
k_main(const float* __restrict__ p0, const float* __restrict__ p1,
       const float* __restrict__ p2, const float* __restrict__ p3,
       const float* __restrict__ p4, const float* __restrict__ p5,
       const float* __restrict__ p6, const float* __restrict__ p7,
       const int* __restrict__ targets,
       float* __restrict__ out,   // [has_scalar + N*8]
       int nrows, int has_scalar)
{
    __shared__ unsigned s_gm[8];

    const int lane = threadIdx.x & 31;
    const int wib  = threadIdx.x >> 5;              // warp in block (0..7)
    const int half = lane >> 4;                     // 0: row A, 1: row B
    const int hl   = lane & 15;                     // lane within half

    const int gwarp  = blockIdx.x * 8 + wib;
    const int nwarps = gridDim.x * 8;

    float* __restrict__ thr = out + has_scalar;
    const float* predsA[4] = {p0, p1, p2, p3};
    const float* predsB[4] = {p4, p5, p6, p7};

    float gm = -3.402823466e38f;   // running max over predictors 0..6

    const int npairs = (nrows + 1) >> 1;

    // ---- prologue: prefetch batch0 (preds 0-3) of the first pair ----
    float4 A0[4], A1[4], B0[4], B1[4];   // ping-pong: (A0,A1)=batch0, (B0,B1)=batch1
    {
        int row0 = gwarp * 2 + half;
        int rs = (row0 < nrows) ? row0 : (nrows - 1);
        load_batch(A0, A1, predsA, (size_t)rs * kC + hl * 8);
    }

    for (int pair = gwarp; pair < npairs; pair += nwarps) {
        const int row = pair * 2 + half;
        const bool rowok = (row < nrows);
        const int rsafe = rowok ? row : (nrows - 1);

        const int t = __ldg(targets + rsafe);
        const int towner = t >> 3;       // lane-in-half holding the target
        const int tq     = (t >> 2) & 1; // which float4
        const int tsub   = t & 3;        // element within float4

        const size_t base = (size_t)rsafe * kC + hl * 8;

        // issue batch1 loads NOW; they fly during batch0 compute
        load_batch(B0, B1, predsB, base);

        float m[8], M1;
#pragma unroll
        for (int p = 0; p < 4; p++) {
            m[p] = margin16(A0[p], A1[p], towner, tq, tsub, M1);
            if (rowok) gm = fmaxf(gm, M1);           // preds 0-3 all count
        }

        // issue next pair's batch0 loads; they fly during batch1 compute
        {
            int rown = (pair + nwarps) * 2 + half;
            if (rown >= nrows) rown = nrows - 1;
            load_batch(A0, A1, predsA, (size_t)rown * kC + hl * 8);
        }

#pragma unroll
        for (int p = 0; p < 4; p++) {
            m[4 + p] = margin16(B0[p], B1[p], towner, tq, tsub, M1);
            if (p < 3 && rowok) gm = fmaxf(gm, M1);  // pred 7 (mimic): no gm
        }

        // softmax over the 8 margins, T=2 (redundant across the half)
        float mm = m[0];
#pragma unroll
        for (int p = 1; p < 8; p++) mm = fmaxf(mm, m[p]);
        float e[8], s = 0.0f;
#pragma unroll
        for (int p = 0; p < 8; p++) { e[p] = __expf((m[p] - mm) * 0.5f); s += e[p]; }
        const float inv = 1.0f / s;

        if (hl < 8 && rowok) {
            float mine = (hl == 0) ? e[0] : (hl == 1) ? e[1]
                       : (hl == 2) ? e[2] : (hl == 3) ? e[3]
                       : (hl == 4) ? e[4] : (hl == 5) ? e[5]
                       : (hl == 6) ? e[6] : e[7];
            thr[(size_t)row * 8 + hl] = mine * inv;
        }
    }

    // ---- global-max finalize in the same kernel (last-block ticket) ----
    gm = fmaxf(gm, __shfl_xor_sync(0xffffffffu, gm, 16));  // merge both halves
    if (lane == 0) s_gm[wib] = f2key(gm);
    __syncthreads();
    if (threadIdx.x == 0) {
        unsigned k = s_gm[0];
#pragma unroll
        for (int i = 1; i < 8; i++) k = max(k, s_gm[i]);
        atomicMax(&g_max_key, k);
        __threadfence();
        unsigned old = atomicAdd(&g_ticket, 1u);
        if (old == gridDim.x - 1) {
            unsigned kk = g_max_key;
            if (has_scalar) {
                unsigned u = (kk & 0x80000000u) ? (kk & 0x7FFFFFFFu) : ~kk;
                out[0] = __uint_as_float(u);
            }
            g_max_key = 0u;   // reset for next graph replay
            g_ticket  = 0u;
        }
    }
}

extern "C" void kernel_launch(void* const* d_in, const int* in_sizes, int n_in,
                              void* d_out, int out_size)
{
    const float* p[8];
    for (int i = 0; i < 8; i++) p[i] = (const float*)d_in[i];
    const int* targets = (const int*)d_in[8];
    const int nrows = in_sizes[8];           // targets element count == N

    float* out = (float*)d_out;
    int has_scalar = out_size - nrows * 8;
    if (has_scalar < 0) has_scalar = 0;

    k_main<<<kGrid, 256>>>(p[0], p[1], p[2], p[3], p[4], p[5], p[6], p[7],
                           targets, out, nrows, has_scalar);
}